// round 12
// baseline (speedup 1.0000x reference)
#include <cuda_runtime.h>
#include <cuda_bf16.h>
#include <cuda_fp16.h>
#include <cstdint>
#include <cstddef>

#define NNODE 256
#define NEDGE 4096

typedef unsigned long long ull;

// ---------------- device scratch (no runtime allocation allowed) ------------
__device__ float g_xd [NNODE * 4 * 32 * 32];                    //  4 MB
__device__ float g_agg[NNODE * 4 * 32 * 32];                    //  4 MB
// hidden: channel-last SINGLE fp16, 64 ch: [n][y][x][64]
__device__ __align__(16) __half g_hidf[(size_t)NNODE * 4096 * 64];   // 134 MB
// single-fp16 weights, HMMA B-fragment order, n8-PAIR-fastest (uint4/lane)
__device__ __align__(16) uint4 g_Bf1[18 * 4 * 32];   // conv1 x-part  [chunk<18][p<4][lane]
__device__ __align__(16) uint4 g_Bfu[ 3 * 4 * 32];   // conv1 up-part [chunk<3][p<4][lane]
__device__ __align__(16) uint4 g_Bf2[36 * 2 * 32];   // conv2         [chunk<36][p<2][lane]

// ---------------- helpers ---------------------------------------------------
__device__ __forceinline__ uint32_t smem_u32(const void* p) {
    uint32_t a;
    asm("{ .reg .u64 t; cvta.to.shared.u64 t, %1; cvt.u32.u64 %0, t; }"
        : "=r"(a) : "l"(p));
    return a;
}
__device__ __forceinline__ void ldmx4(uint32_t* r, uint32_t addr) {
    asm volatile("ldmatrix.sync.aligned.m8n8.x4.shared.b16 {%0,%1,%2,%3}, [%4];"
                 : "=r"(r[0]), "=r"(r[1]), "=r"(r[2]), "=r"(r[3]) : "r"(addr));
}
// L2-only 128-bit load (bypass L1 — B fragments are L2-resident and
// warp-redundant; keeping them out of L1 frees wavefronts for A/ldmatrix)
__device__ __forceinline__ uint4 ldcg4(const uint4* p) {
    uint4 v;
    asm volatile("ld.global.cg.v4.u32 {%0,%1,%2,%3}, [%4];"
                 : "=r"(v.x), "=r"(v.y), "=r"(v.z), "=r"(v.w) : "l"(p));
    return v;
}
__device__ __forceinline__ void mma16816f(float* d, const uint32_t* a,
                                          uint32_t b0, uint32_t b1) {
    asm volatile("mma.sync.aligned.m16n8k16.row.col.f32.f16.f16.f32 "
                 "{%0,%1,%2,%3},{%4,%5,%6,%7},{%8,%9},{%0,%1,%2,%3};"
                 : "+f"(d[0]), "+f"(d[1]), "+f"(d[2]), "+f"(d[3])
                 : "r"(a[0]), "r"(a[1]), "r"(a[2]), "r"(a[3]), "r"(b0), "r"(b1));
}
__device__ __forceinline__ uint32_t pkhf(__half a, __half b) {
    __half2 t = __halves2half2(a, b);
    return *reinterpret_cast<uint32_t*>(&t);
}
__device__ __forceinline__ ull pk2(float a, float b) {
    ull r; asm("mov.b64 %0, {%1, %2};" : "=l"(r) : "f"(a), "f"(b)); return r;
}
__device__ __forceinline__ void fma2(ull& d, ull a, ull b) {
    asm("fma.rn.f32x2 %0, %1, %2, %0;" : "+l"(d) : "l"(a), "l"(b));
}
__device__ __forceinline__ void upk2(ull v, float& a, float& b) {
    asm("mov.b64 {%0, %1}, %2;" : "=f"(a), "=f"(b) : "l"(v));
}

// ---------------------------------------------------------------------------
// 1) merged: downsample + zero g_agg (blocks 0..1023)  |  weight prep (1024+)
// ---------------------------------------------------------------------------
__global__ __launch_bounds__(256) void k_down_wprep(const float* __restrict__ x,
                                                    const float* __restrict__ w,
                                                    const float* __restrict__ b,
                                                    const float* __restrict__ w1,
                                                    const float* __restrict__ w2) {
    if (blockIdx.x < 1024) {
        int idx = blockIdx.x * 256 + threadIdx.x;
        int n = idx >> 10, p = (idx >> 5) & 31, q = idx & 31;
        float a0 = __ldg(b + 0), a1 = __ldg(b + 1), a2 = __ldg(b + 2), a3 = __ldg(b + 3);
        const float* xp = x + (size_t)n * 32 * 4096 + (2 * p) * 64 + 2 * q;
        const float4* wq = (const float4*)w;
        #pragma unroll 4
        for (int c = 0; c < 32; ++c) {
            float2 va = __ldg((const float2*)(xp + c * 4096));
            float2 vb = __ldg((const float2*)(xp + c * 4096 + 64));
            float4 w0 = __ldg(wq + c);
            float4 w1v = __ldg(wq + 32 + c);
            float4 w2v = __ldg(wq + 64 + c);
            float4 w3v = __ldg(wq + 96 + c);
            a0 += va.x * w0.x + va.y * w0.y + vb.x * w0.z + vb.y * w0.w;
            a1 += va.x * w1v.x + va.y * w1v.y + vb.x * w1v.z + vb.y * w1v.w;
            a2 += va.x * w2v.x + va.y * w2v.y + vb.x * w2v.z + vb.y * w2v.w;
            a3 += va.x * w3v.x + va.y * w3v.y + vb.x * w3v.z + vb.y * w3v.w;
        }
        float* op = g_xd + n * 4096 + p * 32 + q;
        op[0] = a0; op[1024] = a1; op[2048] = a2; op[3072] = a3;
        float* ap = g_agg + n * 4096 + p * 32 + q;
        ap[0] = 0.f; ap[1024] = 0.f; ap[2048] = 0.f; ap[3072] = 0.f;
        return;
    }
    int i = (blockIdx.x - 1024) * 256 + threadIdx.x;
    if (i < 2304) {                          // conv1 x-part: 18 chunks * 4p * 32
        int chunk = i >> 7, rem = i & 127;
        int p = rem >> 5, lane = rem & 31;
        int t = chunk >> 1, kc = chunk & 1;
        int cb = kc * 16 + ((lane & 3) << 1);
        uint32_t v[4];
        #pragma unroll
        for (int e2 = 0; e2 < 2; ++e2) {
            int o = (2 * p + e2) * 8 + (lane >> 2);
            v[e2 * 2 + 0] = pkhf(__float2half(__ldg(w1 + (size_t)(o * 36 + cb)     * 9 + t)),
                                 __float2half(__ldg(w1 + (size_t)(o * 36 + cb + 1) * 9 + t)));
            v[e2 * 2 + 1] = pkhf(__float2half(__ldg(w1 + (size_t)(o * 36 + cb + 8) * 9 + t)),
                                 __float2half(__ldg(w1 + (size_t)(o * 36 + cb + 9) * 9 + t)));
        }
        g_Bf1[i] = make_uint4(v[0], v[1], v[2], v[3]);
    } else if (i < 2304 + 384) {             // conv1 up-part: 3 chunks * 4p * 32
        int j = i - 2304;
        int chunk = j >> 7, rem = j & 127;
        int p = rem >> 5, lane = rem & 31;
        int k0 = chunk * 16 + ((lane & 3) << 1);
        uint32_t v[4];
        #pragma unroll
        for (int e2 = 0; e2 < 2; ++e2) {
            int o = (2 * p + e2) * 8 + (lane >> 2);
            float f[4];
            #pragma unroll
            for (int q = 0; q < 4; ++q) {
                int k = k0 + (q >> 1) * 8 + (q & 1);
                f[q] = (k < 36)
                     ? __ldg(w1 + (size_t)(o * 36 + 32 + (k & 3)) * 9 + (k >> 2))
                     : 0.f;
            }
            v[e2 * 2 + 0] = pkhf(__float2half(f[0]), __float2half(f[1]));
            v[e2 * 2 + 1] = pkhf(__float2half(f[2]), __float2half(f[3]));
        }
        g_Bfu[j] = make_uint4(v[0], v[1], v[2], v[3]);
    } else if (i < 2688 + 2304) {            // conv2: 36 chunks * 2p * 32
        int j = i - 2688;
        int chunk = j >> 6, rem = j & 63;
        int p = rem >> 5, lane = rem & 31;
        int t = chunk >> 2, kc = chunk & 3;
        int cb = kc * 16 + ((lane & 3) << 1);
        uint32_t v[4];
        #pragma unroll
        for (int e2 = 0; e2 < 2; ++e2) {
            int o = (2 * p + e2) * 8 + (lane >> 2);
            v[e2 * 2 + 0] = pkhf(__float2half(__ldg(w2 + (size_t)(o * 64 + cb)     * 9 + t)),
                                 __float2half(__ldg(w2 + (size_t)(o * 64 + cb + 1) * 9 + t)));
            v[e2 * 2 + 1] = pkhf(__float2half(__ldg(w2 + (size_t)(o * 64 + cb + 8) * 9 + t)),
                                 __float2half(__ldg(w2 + (size_t)(o * 64 + cb + 9) * 9 + t)));
        }
        g_Bf2[j] = make_uint4(v[0], v[1], v[2], v[3]);
    }
}

// ---------------------------------------------------------------------------
// 2) fused edge network + scatter, FFMA2 (validated R10)
// ---------------------------------------------------------------------------
__global__ __launch_bounds__(256) void k_edge(const int* __restrict__ eidx,
                                              const float* __restrict__ we1,
                                              const float* __restrict__ be1,
                                              const float* __restrict__ we2,
                                              const float* __restrict__ be2) {
    __shared__ float sIn[8][34][34];
    const int e = blockIdx.x;
    const int row = eidx[e];
    const int col = eidx[NEDGE + e];
    const int tid = threadIdx.x;

    for (int i = tid; i < 1056; i += 256) {
        int ch = i / 132, r = i - ch * 132;
        int py, px;
        if (r < 34)      { py = 0;  px = r; }
        else if (r < 68) { py = 33; px = r - 34; }
        else { int rr = r - 68; py = 1 + (rr >> 1); px = (rr & 1) ? 33 : 0; }
        sIn[ch][py][px] = 0.f;
    }
    for (int i = tid; i < 2048; i += 256) {
        int ch = i >> 8, p4 = i & 255;
        int node = (ch < 4) ? row : col;
        float4 v = __ldg((const float4*)(g_xd + node * 4096 + (ch & 3) * 1024) + p4);
        int py = p4 >> 3, px = (p4 & 7) << 2;
        float* d = &sIn[ch][py + 1][px + 1];
        d[0] = v.x; d[1] = v.y; d[2] = v.z; d[3] = v.w;
    }
    __syncthreads();

    const int og   = tid >> 7;
    const int unit = tid & 127;
    const int ry   = unit >> 2;
    const int cx0  = (unit & 3) << 3;
    const int o0 = og * 2, o1 = og * 2 + 1;

    ull acc1[8];
    { ull bp = pk2(__ldg(be1 + o0), __ldg(be1 + o1));
      #pragma unroll
      for (int j = 0; j < 8; ++j) acc1[j] = bp; }
    #pragma unroll
    for (int ci = 0; ci < 8; ++ci) {
        ull v[3][10];
        #pragma unroll
        for (int d = 0; d < 3; ++d)
            #pragma unroll
            for (int c = 0; c < 10; ++c) {
                float f = sIn[ci][ry + d][cx0 + c];
                v[d][c] = pk2(f, f);
            }
        #pragma unroll
        for (int t = 0; t < 9; ++t) {
            int dy = t / 3, dx = t - dy * 3;
            ull wp = pk2(__ldg(we1 + o0 * 72 + ci * 9 + t),
                         __ldg(we1 + o1 * 72 + ci * 9 + t));
            #pragma unroll
            for (int j = 0; j < 8; ++j) fma2(acc1[j], v[dy][dx + j], wp);
        }
    }
    __syncthreads();
    #pragma unroll
    for (int j = 0; j < 8; ++j) {
        float a, b; upk2(acc1[j], a, b);
        sIn[o0][ry + 1][cx0 + 1 + j] = fmaxf(a, 0.f);
        sIn[o1][ry + 1][cx0 + 1 + j] = fmaxf(b, 0.f);
    }
    __syncthreads();

    ull acc2[8];
    { ull bp = pk2(__ldg(be2 + o0), __ldg(be2 + o1));
      #pragma unroll
      for (int j = 0; j < 8; ++j) acc2[j] = bp; }
    #pragma unroll
    for (int ci = 0; ci < 4; ++ci) {
        ull v[3][10];
        #pragma unroll
        for (int d = 0; d < 3; ++d)
            #pragma unroll
            for (int c = 0; c < 10; ++c) {
                float f = sIn[ci][ry + d][cx0 + c];
                v[d][c] = pk2(f, f);
            }
        #pragma unroll
        for (int t = 0; t < 9; ++t) {
            int dy = t / 3, dx = t - dy * 3;
            ull wp = pk2(__ldg(we2 + o0 * 36 + ci * 9 + t),
                         __ldg(we2 + o1 * 36 + ci * 9 + t));
            #pragma unroll
            for (int j = 0; j < 8; ++j) fma2(acc2[j], v[dy][dx + j], wp);
        }
    }
    float* ag0 = g_agg + row * 4096 + o0 * 1024 + ry * 32 + cx0;
    float* ag1 = g_agg + row * 4096 + o1 * 1024 + ry * 32 + cx0;
    #pragma unroll
    for (int j = 0; j < 8; ++j) {
        float a, b; upk2(acc2[j], a, b);
        atomicAdd(ag0 + j, fmaxf(a, 0.f));
        atomicAdd(ag1 + j, fmaxf(b, 0.f));
    }
}

// ---------------------------------------------------------------------------
// 3) conv1: R10 structure (256 thr, mb=2, n8=8), B via ld.global.cg
// ---------------------------------------------------------------------------
__global__ __launch_bounds__(256, 2)
void k_conv1(const float* __restrict__ x,
             const float* __restrict__ wup, const float* __restrict__ bup,
             const uint4* __restrict__ bf1, const uint4* __restrict__ bfu,
             const float* __restrict__ bias) {
    extern __shared__ __align__(16) char smw[];
    char*  winx = smw;                       // 396*80  = 31680 B
    float* winu = (float*)(smw + 31680);     // 396*16  =  6336 B
    char*  uim  = smw + 38016;               // 256*112 = 28672 B

    const int tid = threadIdx.x;
    const int n  = blockIdx.x >> 4;
    const int y0 = (blockIdx.x & 15) << 2;

    for (int i = tid; i < 396; i += 256) {
        int wy = i / 66, wx = i - wy * 66;
        int gy = y0 + wy - 1, gx = wx - 1;
        uint4*  dx4 = (uint4*)(winx + i * 80);
        float4* du  = (float4*)(winu + i * 4);
        if ((unsigned)gy < 64u && (unsigned)gx < 64u) {
            const float* ag = g_agg + n * 4096 + (gy >> 1) * 32 + (gx >> 1);
            const int ab = ((gy & 1) << 1) + (gx & 1);
            float up[4];
            #pragma unroll
            for (int o = 0; o < 4; ++o) {
                float v = __ldg(bup + o);
                #pragma unroll
                for (int c = 0; c < 4; ++c)
                    v += ag[c * 1024] * __ldg(wup + ((c * 4 + o) << 2) + ab);
                up[o] = v;
            }
            *du = make_float4(up[0], up[1], up[2], up[3]);
            uint32_t ph[16];
            const float* xp = x + (size_t)n * 32 * 4096 + gy * 64 + gx;
            #pragma unroll
            for (int c2 = 0; c2 < 16; ++c2)
                ph[c2] = pkhf(__float2half(__ldg(xp + (2 * c2) * 4096)),
                              __float2half(__ldg(xp + (2 * c2 + 1) * 4096)));
            #pragma unroll
            for (int u = 0; u < 4; ++u)
                dx4[u] = make_uint4(ph[4 * u], ph[4 * u + 1], ph[4 * u + 2], ph[4 * u + 3]);
        } else {
            uint4 z = make_uint4(0, 0, 0, 0);
            #pragma unroll
            for (int u = 0; u < 4; ++u) dx4[u] = z;
            *du = make_float4(0.f, 0.f, 0.f, 0.f);
        }
    }
    __syncthreads();

    {   // im2col up channels: uim[px][tap*4+ch] fp16, pads zero
        int r = tid >> 6, xx = tid & 63;
        uint32_t arr[28];
        #pragma unroll
        for (int t9 = 0; t9 < 9; ++t9) {
            int dy = t9 / 3, dxp = t9 - dy * 3;
            const float* u4 = winu + ((r + dy) * 66 + xx + dxp) * 4;
            arr[t9 * 2 + 0] = pkhf(__float2half(u4[0]), __float2half(u4[1]));
            arr[t9 * 2 + 1] = pkhf(__float2half(u4[2]), __float2half(u4[3]));
        }
        #pragma unroll
        for (int j = 18; j < 28; ++j) arr[j] = 0u;
        uint4* du = (uint4*)(uim + tid * 112);
        #pragma unroll
        for (int u = 0; u < 7; ++u)
            du[u] = make_uint4(arr[4 * u], arr[4 * u + 1], arr[4 * u + 2], arr[4 * u + 3]);
    }
    __syncthreads();

    const int w = tid >> 5, lane = tid & 31;
    const int rw = w >> 1, colbase = (w & 1) << 5;
    const int t4 = lane >> 3, rowin = lane & 7;
    const int mloc = ((t4 & 1) << 3) + rowin;
    const uint32_t kbyte = (uint32_t)(t4 >> 1) * 16;
    const uint32_t wbx = smem_u32(winx);
    const uint32_t wbu = smem_u32(uim);
    uint32_t baseA[2], baseU[2];
    #pragma unroll
    for (int mb = 0; mb < 2; ++mb) {
        int c = colbase + mb * 16 + mloc;
        baseA[mb] = wbx + (uint32_t)(rw * 66 + c) * 80 + kbyte;
        baseU[mb] = wbu + (uint32_t)(rw * 64 + c) * 112 + kbyte;
    }

    const int cb = (lane & 3) << 1;
    float acc[2][8][4];
    #pragma unroll
    for (int n8 = 0; n8 < 8; ++n8) {
        float b0 = __ldg(bias + n8 * 8 + cb);
        float b1 = __ldg(bias + n8 * 8 + cb + 1);
        #pragma unroll
        for (int mb = 0; mb < 2; ++mb) {
            acc[mb][n8][0] = b0; acc[mb][n8][1] = b1;
            acc[mb][n8][2] = b0; acc[mb][n8][3] = b1;
        }
    }

    for (int t = 0; t < 9; ++t) {
        const int dy = t / 3, dxp = t - dy * 3;
        const uint32_t tapoff = (uint32_t)(dy * 66 + dxp) * 80;
        #pragma unroll
        for (int kc = 0; kc < 2; ++kc) {
            uint32_t ah[2][4];
            #pragma unroll
            for (int mb = 0; mb < 2; ++mb)
                ldmx4(ah[mb], baseA[mb] + tapoff + (uint32_t)kc * 32);
            const uint4* bp = bf1 + ((t * 2 + kc) * 4) * 32 + lane;
            #pragma unroll
            for (int p = 0; p < 4; ++p) {
                uint4 bq = ldcg4(bp + p * 32);
                #pragma unroll
                for (int mb = 0; mb < 2; ++mb) {
                    mma16816f(acc[mb][2 * p],     ah[mb], bq.x, bq.y);
                    mma16816f(acc[mb][2 * p + 1], ah[mb], bq.z, bq.w);
                }
            }
        }
    }
    #pragma unroll
    for (int kc = 0; kc < 3; ++kc) {
        uint32_t ah[2][4];
        #pragma unroll
        for (int mb = 0; mb < 2; ++mb)
            ldmx4(ah[mb], baseU[mb] + (uint32_t)kc * 32);
        const uint4* bp = bfu + (kc * 4) * 32 + lane;
        #pragma unroll
        for (int p = 0; p < 4; ++p) {
            uint4 bq = ldcg4(bp + p * 32);
            #pragma unroll
            for (int mb = 0; mb < 2; ++mb) {
                mma16816f(acc[mb][2 * p],     ah[mb], bq.x, bq.y);
                mma16816f(acc[mb][2 * p + 1], ah[mb], bq.z, bq.w);
            }
        }
    }

    #pragma unroll
    for (int mb = 0; mb < 2; ++mb) {
        #pragma unroll
        for (int half = 0; half < 2; ++half) {
            int ox = colbase + mb * 16 + (lane >> 2) + half * 8;
            int oy = y0 + rw;
            size_t pix = ((size_t)(n * 64 + oy) * 64 + ox);
            uint32_t* oh = reinterpret_cast<uint32_t*>(g_hidf) + pix * 32 + (cb >> 1);
            #pragma unroll
            for (int n8 = 0; n8 < 8; ++n8) {
                float v0 = fmaxf(acc[mb][n8][half * 2 + 0], 0.f);
                float v1 = fmaxf(acc[mb][n8][half * 2 + 1], 0.f);
                oh[n8 * 4] = pkhf(__float2half(v0), __float2half(v1));
            }
        }
    }
}

// ---------------------------------------------------------------------------
// 4) conv2: R10 structure (256 thr, mb=2, n8=4), B via ld.global.cg
// ---------------------------------------------------------------------------
__global__ __launch_bounds__(256, 2)
void k_conv2(const uint4* __restrict__ inf,
             const uint4* __restrict__ bf2,
             const float* __restrict__ bias, float* __restrict__ out32) {
    extern __shared__ __align__(16) char smw[];
    constexpr int WS = 72;
    constexpr int WPIX = 6 * 66;
    __half* winf = (__half*)smw;

    const int tid = threadIdx.x;
    const int n  = blockIdx.x >> 4;
    const int y0 = (blockIdx.x & 15) << 2;

    for (int i = tid; i < WPIX; i += 256) {
        int wy = i / 66, wx = i - wy * 66;
        int gy = y0 + wy - 1, gx = wx - 1;
        uint4* df = (uint4*)(winf + i * WS);
        if ((unsigned)gy < 64u && (unsigned)gx < 64u) {
            size_t s = ((size_t)(n * 64 + gy) * 64 + gx) * 8;
            #pragma unroll
            for (int u = 0; u < 8; ++u) df[u] = __ldg(inf + s + u);
        } else {
            uint4 z = make_uint4(0, 0, 0, 0);
            #pragma unroll
            for (int u = 0; u < 8; ++u) df[u] = z;
        }
    }
    __syncthreads();

    const int w = tid >> 5, lane = tid & 31;
    const int rw = w >> 1, colbase = (w & 1) << 5;
    const int t4 = lane >> 3, rowin = lane & 7;
    const int mloc = ((t4 & 1) << 3) + rowin;
    const uint32_t kbyte = (uint32_t)(t4 >> 1) * 16;
    const uint32_t wbh = smem_u32(winf);
    uint32_t baseA[2];
    #pragma unroll
    for (int mb = 0; mb < 2; ++mb) {
        int xx = colbase + mb * 16 + mloc;
        baseA[mb] = wbh + (uint32_t)(rw * 66 + xx) * (WS * 2) + kbyte;
    }

    const int cb = (lane & 3) << 1;
    float acc[2][4][4];
    #pragma unroll
    for (int n8 = 0; n8 < 4; ++n8) {
        float b0 = __ldg(bias + n8 * 8 + cb);
        float b1 = __ldg(bias + n8 * 8 + cb + 1);
        #pragma unroll
        for (int mb = 0; mb < 2; ++mb) {
            acc[mb][n8][0] = b0; acc[mb][n8][1] = b1;
            acc[mb][n8][2] = b0; acc[mb][n8][3] = b1;
        }
    }

    for (int t = 0; t < 9; ++t) {
        const int dy = t / 3, dxp = t - dy * 3;
        const uint32_t tapoff = (uint32_t)(dy * 66 + dxp) * (WS * 2);
        #pragma unroll
        for (int kc = 0; kc < 4; ++kc) {
            uint32_t ah[2][4];
            #pragma unroll
            for (int mb = 0; mb < 2; ++mb)
                ldmx4(ah[mb], baseA[mb] + tapoff + (uint32_t)kc * 32);
            const uint4* bp = bf2 + ((t * 4 + kc) * 2) * 32 + lane;
            #pragma unroll
            for (int p = 0; p < 2; ++p) {
                uint4 bq = ldcg4(bp + p * 32);
                #pragma unroll
                for (int mb = 0; mb < 2; ++mb) {
                    mma16816f(acc[mb][2 * p],     ah[mb], bq.x, bq.y);
                    mma16816f(acc[mb][2 * p + 1], ah[mb], bq.z, bq.w);
                }
            }
        }
    }

    #pragma unroll
    for (int mb = 0; mb < 2; ++mb) {
        #pragma unroll
        for (int half = 0; half < 2; ++half) {
            int ox = colbase + mb * 16 + (lane >> 2) + half * 8;
            int oy = y0 + rw;
            float* ob = out32 + (size_t)n * 32 * 4096 + (size_t)oy * 64 + ox;
            #pragma unroll
            for (int n8 = 0; n8 < 4; ++n8) {
                int ch = n8 * 8 + cb;
                ob[(size_t)ch * 4096]       = acc[mb][n8][half * 2 + 0];
                ob[(size_t)(ch + 1) * 4096] = acc[mb][n8][half * 2 + 1];
            }
        }
    }
}

// ---------------------------------------------------------------------------
extern "C" void kernel_launch(void* const* d_in, const int* in_sizes, int n_in,
                              void* d_out, int out_size) {
    const float* x      = (const float*)d_in[0];
    const int*   eidx   = (const int*)  d_in[1];
    const float* w_down = (const float*)d_in[3];
    const float* b_down = (const float*)d_in[4];
    const float* w_e1   = (const float*)d_in[5];
    const float* b_e1   = (const float*)d_in[6];
    const float* w_e2   = (const float*)d_in[7];
    const float* b_e2   = (const float*)d_in[8];
    const float* w_up   = (const float*)d_in[9];
    const float* b_up   = (const float*)d_in[10];
    const float* w_n1   = (const float*)d_in[11];
    const float* b_n1   = (const float*)d_in[12];
    const float* w_n2   = (const float*)d_in[13];
    const float* b_n2   = (const float*)d_in[14];
    float* out = (float*)d_out;

    void *p_hidf, *p_B1, *p_Bu, *p_B2;
    cudaGetSymbolAddress(&p_hidf, g_hidf);
    cudaGetSymbolAddress(&p_B1, g_Bf1);
    cudaGetSymbolAddress(&p_Bu, g_Bfu);
    cudaGetSymbolAddress(&p_B2, g_Bf2);

    const int sm1 = 31680 + 6336 + 28672;   // 66688 B
    const int sm2 = 6 * 66 * 72 * 2;        // 57024 B
    cudaFuncSetAttribute((const void*)k_conv1,
                         cudaFuncAttributeMaxDynamicSharedMemorySize, sm1);
    cudaFuncSetAttribute((const void*)k_conv2,
                         cudaFuncAttributeMaxDynamicSharedMemorySize, sm2);

    // 1) downsample (+zero g_agg) fused with weight prep (blocks 1024..1043)
    k_down_wprep<<<1044, 256>>>(x, w_down, b_down, w_n1, w_n2);
    // 2) fused edge network + scatter-add (FFMA2)
    k_edge<<<NEDGE, 256>>>(eidx, w_e1, b_e1, w_e2, b_e2);
    // 3) conv1: R10 tiling, B via L2-only loads
    k_conv1<<<4096, 256, sm1>>>(x, w_up, b_up,
        (const uint4*)p_B1, (const uint4*)p_Bu, b_n1);
    // 4) conv2: R10 tiling, B via L2-only loads
    k_conv2<<<4096, 256, sm2>>>((const uint4*)p_hidf,
        (const uint4*)p_B2, b_n2, out);
}

// round 13
// speedup vs baseline: 1.0220x; 1.0220x over previous
#include <cuda_runtime.h>
#include <cuda_bf16.h>
#include <cuda_fp16.h>
#include <cstdint>
#include <cstddef>

#define NNODE 256
#define NEDGE 4096

typedef unsigned long long ull;

// ---------------- device scratch (no runtime allocation allowed) ------------
__device__ float g_xd [NNODE * 4 * 32 * 32];                    //  4 MB
__device__ float g_agg[NNODE * 4 * 32 * 32];                    //  4 MB
// hidden: fp16, 64 ch per pixel, FRAGMENT-NATIVE word order:
//   word W (uint32) = q*8 + n8 holds channel pair c = 2*(n8*4+q), c+1
__device__ __align__(16) __half g_hidf[(size_t)NNODE * 4096 * 64];   // 134 MB
// single-fp16 weights, HMMA B-fragment order, n8-PAIR-fastest (uint4/lane)
__device__ __align__(16) uint4 g_Bf1[18 * 4 * 32];   // conv1 x-part  [chunk<18][p<4][lane]
__device__ __align__(16) uint4 g_Bfu[ 3 * 4 * 32];   // conv1 up-part [chunk<3][p<4][lane]
__device__ __align__(16) uint4 g_Bf2[36 * 2 * 32];   // conv2         [chunk<36][p<2][lane]

// ---------------- helpers ---------------------------------------------------
__device__ __forceinline__ uint32_t smem_u32(const void* p) {
    uint32_t a;
    asm("{ .reg .u64 t; cvta.to.shared.u64 t, %1; cvt.u32.u64 %0, t; }"
        : "=r"(a) : "l"(p));
    return a;
}
__device__ __forceinline__ void ldmx4(uint32_t* r, uint32_t addr) {
    asm volatile("ldmatrix.sync.aligned.m8n8.x4.shared.b16 {%0,%1,%2,%3}, [%4];"
                 : "=r"(r[0]), "=r"(r[1]), "=r"(r[2]), "=r"(r[3]) : "r"(addr));
}
__device__ __forceinline__ void mma16816f(float* d, const uint32_t* a,
                                          uint32_t b0, uint32_t b1) {
    asm volatile("mma.sync.aligned.m16n8k16.row.col.f32.f16.f16.f32 "
                 "{%0,%1,%2,%3},{%4,%5,%6,%7},{%8,%9},{%0,%1,%2,%3};"
                 : "+f"(d[0]), "+f"(d[1]), "+f"(d[2]), "+f"(d[3])
                 : "r"(a[0]), "r"(a[1]), "r"(a[2]), "r"(a[3]), "r"(b0), "r"(b1));
}
__device__ __forceinline__ uint32_t pkhf(__half a, __half b) {
    __half2 t = __halves2half2(a, b);
    return *reinterpret_cast<uint32_t*>(&t);
}
__device__ __forceinline__ ull pk2(float a, float b) {
    ull r; asm("mov.b64 %0, {%1, %2};" : "=l"(r) : "f"(a), "f"(b)); return r;
}
__device__ __forceinline__ void fma2(ull& d, ull a, ull b) {
    asm("fma.rn.f32x2 %0, %1, %2, %0;" : "+l"(d) : "l"(a), "l"(b));
}
__device__ __forceinline__ void upk2(ull v, float& a, float& b) {
    asm("mov.b64 {%0, %1}, %2;" : "=f"(a), "=f"(b) : "l"(v));
}

// ---------------------------------------------------------------------------
// 1) merged: downsample + zero g_agg (blocks 0..1023)  |  weight prep (1024+)
// ---------------------------------------------------------------------------
__global__ __launch_bounds__(256) void k_down_wprep(const float* __restrict__ x,
                                                    const float* __restrict__ w,
                                                    const float* __restrict__ b,
                                                    const float* __restrict__ w1,
                                                    const float* __restrict__ w2) {
    if (blockIdx.x < 1024) {
        int idx = blockIdx.x * 256 + threadIdx.x;
        int n = idx >> 10, p = (idx >> 5) & 31, q = idx & 31;
        float a0 = __ldg(b + 0), a1 = __ldg(b + 1), a2 = __ldg(b + 2), a3 = __ldg(b + 3);
        const float* xp = x + (size_t)n * 32 * 4096 + (2 * p) * 64 + 2 * q;
        const float4* wq = (const float4*)w;
        #pragma unroll 4
        for (int c = 0; c < 32; ++c) {
            float2 va = __ldg((const float2*)(xp + c * 4096));
            float2 vb = __ldg((const float2*)(xp + c * 4096 + 64));
            float4 w0 = __ldg(wq + c);
            float4 w1v = __ldg(wq + 32 + c);
            float4 w2v = __ldg(wq + 64 + c);
            float4 w3v = __ldg(wq + 96 + c);
            a0 += va.x * w0.x + va.y * w0.y + vb.x * w0.z + vb.y * w0.w;
            a1 += va.x * w1v.x + va.y * w1v.y + vb.x * w1v.z + vb.y * w1v.w;
            a2 += va.x * w2v.x + va.y * w2v.y + vb.x * w2v.z + vb.y * w2v.w;
            a3 += va.x * w3v.x + va.y * w3v.y + vb.x * w3v.z + vb.y * w3v.w;
        }
        float* op = g_xd + n * 4096 + p * 32 + q;
        op[0] = a0; op[1024] = a1; op[2048] = a2; op[3072] = a3;
        float* ap = g_agg + n * 4096 + p * 32 + q;
        ap[0] = 0.f; ap[1024] = 0.f; ap[2048] = 0.f; ap[3072] = 0.f;
        return;
    }
    int i = (blockIdx.x - 1024) * 256 + threadIdx.x;
    if (i < 2304) {                          // conv1 x-part: 18 chunks * 4p * 32
        int chunk = i >> 7, rem = i & 127;
        int p = rem >> 5, lane = rem & 31;
        int t = chunk >> 1, kc = chunk & 1;
        int cb = kc * 16 + ((lane & 3) << 1);
        uint32_t v[4];
        #pragma unroll
        for (int e2 = 0; e2 < 2; ++e2) {
            int o = (2 * p + e2) * 8 + (lane >> 2);
            v[e2 * 2 + 0] = pkhf(__float2half(__ldg(w1 + (size_t)(o * 36 + cb)     * 9 + t)),
                                 __float2half(__ldg(w1 + (size_t)(o * 36 + cb + 1) * 9 + t)));
            v[e2 * 2 + 1] = pkhf(__float2half(__ldg(w1 + (size_t)(o * 36 + cb + 8) * 9 + t)),
                                 __float2half(__ldg(w1 + (size_t)(o * 36 + cb + 9) * 9 + t)));
        }
        g_Bf1[i] = make_uint4(v[0], v[1], v[2], v[3]);
    } else if (i < 2304 + 384) {             // conv1 up-part: 3 chunks * 4p * 32
        int j = i - 2304;
        int chunk = j >> 7, rem = j & 127;
        int p = rem >> 5, lane = rem & 31;
        int k0 = chunk * 16 + ((lane & 3) << 1);
        uint32_t v[4];
        #pragma unroll
        for (int e2 = 0; e2 < 2; ++e2) {
            int o = (2 * p + e2) * 8 + (lane >> 2);
            float f[4];
            #pragma unroll
            for (int q = 0; q < 4; ++q) {
                int k = k0 + (q >> 1) * 8 + (q & 1);
                f[q] = (k < 36)
                     ? __ldg(w1 + (size_t)(o * 36 + 32 + (k & 3)) * 9 + (k >> 2))
                     : 0.f;
            }
            v[e2 * 2 + 0] = pkhf(__float2half(f[0]), __float2half(f[1]));
            v[e2 * 2 + 1] = pkhf(__float2half(f[2]), __float2half(f[3]));
        }
        g_Bfu[j] = make_uint4(v[0], v[1], v[2], v[3]);
    } else if (i < 2688 + 2304) {            // conv2: 36 chunks * 2p * 32
        // hidden is fragment-native permuted: for chunk kc, frag k-position k:
        //   channel(kc,k) = (k>>1)*8 + kc*2 + (k&1)
        // lane supplies k = (lane&3)*2 {+1} (b.x) and +8 {+9} (b.y):
        //   b.x -> channels c0, c0+1 with c0 = (lane&3)*8 + kc*2
        //   b.y -> channels c0+32, c0+33
        int j = i - 2688;
        int chunk = j >> 6, rem = j & 63;
        int p = rem >> 5, lane = rem & 31;
        int t = chunk >> 2, kc = chunk & 3;
        int c0 = ((lane & 3) << 3) + kc * 2;
        uint32_t v[4];
        #pragma unroll
        for (int e2 = 0; e2 < 2; ++e2) {
            int o = (2 * p + e2) * 8 + (lane >> 2);
            v[e2 * 2 + 0] = pkhf(__float2half(__ldg(w2 + (size_t)(o * 64 + c0)      * 9 + t)),
                                 __float2half(__ldg(w2 + (size_t)(o * 64 + c0 + 1)  * 9 + t)));
            v[e2 * 2 + 1] = pkhf(__float2half(__ldg(w2 + (size_t)(o * 64 + c0 + 32) * 9 + t)),
                                 __float2half(__ldg(w2 + (size_t)(o * 64 + c0 + 33) * 9 + t)));
        }
        g_Bf2[j] = make_uint4(v[0], v[1], v[2], v[3]);
    }
}

// ---------------------------------------------------------------------------
// 2) fused edge network + scatter, FFMA2 (validated R10)
// ---------------------------------------------------------------------------
__global__ __launch_bounds__(256) void k_edge(const int* __restrict__ eidx,
                                              const float* __restrict__ we1,
                                              const float* __restrict__ be1,
                                              const float* __restrict__ we2,
                                              const float* __restrict__ be2) {
    __shared__ float sIn[8][34][34];
    const int e = blockIdx.x;
    const int row = eidx[e];
    const int col = eidx[NEDGE + e];
    const int tid = threadIdx.x;

    for (int i = tid; i < 1056; i += 256) {
        int ch = i / 132, r = i - ch * 132;
        int py, px;
        if (r < 34)      { py = 0;  px = r; }
        else if (r < 68) { py = 33; px = r - 34; }
        else { int rr = r - 68; py = 1 + (rr >> 1); px = (rr & 1) ? 33 : 0; }
        sIn[ch][py][px] = 0.f;
    }
    for (int i = tid; i < 2048; i += 256) {
        int ch = i >> 8, p4 = i & 255;
        int node = (ch < 4) ? row : col;
        float4 v = __ldg((const float4*)(g_xd + node * 4096 + (ch & 3) * 1024) + p4);
        int py = p4 >> 3, px = (p4 & 7) << 2;
        float* d = &sIn[ch][py + 1][px + 1];
        d[0] = v.x; d[1] = v.y; d[2] = v.z; d[3] = v.w;
    }
    __syncthreads();

    const int og   = tid >> 7;
    const int unit = tid & 127;
    const int ry   = unit >> 2;
    const int cx0  = (unit & 3) << 3;
    const int o0 = og * 2, o1 = og * 2 + 1;

    ull acc1[8];
    { ull bp = pk2(__ldg(be1 + o0), __ldg(be1 + o1));
      #pragma unroll
      for (int j = 0; j < 8; ++j) acc1[j] = bp; }
    #pragma unroll
    for (int ci = 0; ci < 8; ++ci) {
        ull v[3][10];
        #pragma unroll
        for (int d = 0; d < 3; ++d)
            #pragma unroll
            for (int c = 0; c < 10; ++c) {
                float f = sIn[ci][ry + d][cx0 + c];
                v[d][c] = pk2(f, f);
            }
        #pragma unroll
        for (int t = 0; t < 9; ++t) {
            int dy = t / 3, dx = t - dy * 3;
            ull wp = pk2(__ldg(we1 + o0 * 72 + ci * 9 + t),
                         __ldg(we1 + o1 * 72 + ci * 9 + t));
            #pragma unroll
            for (int j = 0; j < 8; ++j) fma2(acc1[j], v[dy][dx + j], wp);
        }
    }
    __syncthreads();
    #pragma unroll
    for (int j = 0; j < 8; ++j) {
        float a, b; upk2(acc1[j], a, b);
        sIn[o0][ry + 1][cx0 + 1 + j] = fmaxf(a, 0.f);
        sIn[o1][ry + 1][cx0 + 1 + j] = fmaxf(b, 0.f);
    }
    __syncthreads();

    ull acc2[8];
    { ull bp = pk2(__ldg(be2 + o0), __ldg(be2 + o1));
      #pragma unroll
      for (int j = 0; j < 8; ++j) acc2[j] = bp; }
    #pragma unroll
    for (int ci = 0; ci < 4; ++ci) {
        ull v[3][10];
        #pragma unroll
        for (int d = 0; d < 3; ++d)
            #pragma unroll
            for (int c = 0; c < 10; ++c) {
                float f = sIn[ci][ry + d][cx0 + c];
                v[d][c] = pk2(f, f);
            }
        #pragma unroll
        for (int t = 0; t < 9; ++t) {
            int dy = t / 3, dx = t - dy * 3;
            ull wp = pk2(__ldg(we2 + o0 * 36 + ci * 9 + t),
                         __ldg(we2 + o1 * 36 + ci * 9 + t));
            #pragma unroll
            for (int j = 0; j < 8; ++j) fma2(acc2[j], v[dy][dx + j], wp);
        }
    }
    float* ag0 = g_agg + row * 4096 + o0 * 1024 + ry * 32 + cx0;
    float* ag1 = g_agg + row * 4096 + o1 * 1024 + ry * 32 + cx0;
    #pragma unroll
    for (int j = 0; j < 8; ++j) {
        float a, b; upk2(acc2[j], a, b);
        atomicAdd(ag0 + j, fmaxf(a, 0.f));
        atomicAdd(ag1 + j, fmaxf(b, 0.f));
    }
}

// ---------------------------------------------------------------------------
// 3) conv1: R10 structure (256 thr, mb=2, n8=8), B via __ldg,
//    epilogue = 2x STG.128 per (mb,half) into fragment-native hidden.
// ---------------------------------------------------------------------------
__global__ __launch_bounds__(256, 2)
void k_conv1(const float* __restrict__ x,
             const float* __restrict__ wup, const float* __restrict__ bup,
             const uint4* __restrict__ bf1, const uint4* __restrict__ bfu,
             const float* __restrict__ bias) {
    extern __shared__ __align__(16) char smw[];
    char*  winx = smw;                       // 396*80  = 31680 B
    float* winu = (float*)(smw + 31680);     // 396*16  =  6336 B
    char*  uim  = smw + 38016;               // 256*112 = 28672 B

    const int tid = threadIdx.x;
    const int n  = blockIdx.x >> 4;
    const int y0 = (blockIdx.x & 15) << 2;

    for (int i = tid; i < 396; i += 256) {
        int wy = i / 66, wx = i - wy * 66;
        int gy = y0 + wy - 1, gx = wx - 1;
        uint4*  dx4 = (uint4*)(winx + i * 80);
        float4* du  = (float4*)(winu + i * 4);
        if ((unsigned)gy < 64u && (unsigned)gx < 64u) {
            const float* ag = g_agg + n * 4096 + (gy >> 1) * 32 + (gx >> 1);
            const int ab = ((gy & 1) << 1) + (gx & 1);
            float up[4];
            #pragma unroll
            for (int o = 0; o < 4; ++o) {
                float v = __ldg(bup + o);
                #pragma unroll
                for (int c = 0; c < 4; ++c)
                    v += ag[c * 1024] * __ldg(wup + ((c * 4 + o) << 2) + ab);
                up[o] = v;
            }
            *du = make_float4(up[0], up[1], up[2], up[3]);
            uint32_t ph[16];
            const float* xp = x + (size_t)n * 32 * 4096 + gy * 64 + gx;
            #pragma unroll
            for (int c2 = 0; c2 < 16; ++c2)
                ph[c2] = pkhf(__float2half(__ldg(xp + (2 * c2) * 4096)),
                              __float2half(__ldg(xp + (2 * c2 + 1) * 4096)));
            #pragma unroll
            for (int u = 0; u < 4; ++u)
                dx4[u] = make_uint4(ph[4 * u], ph[4 * u + 1], ph[4 * u + 2], ph[4 * u + 3]);
        } else {
            uint4 z = make_uint4(0, 0, 0, 0);
            #pragma unroll
            for (int u = 0; u < 4; ++u) dx4[u] = z;
            *du = make_float4(0.f, 0.f, 0.f, 0.f);
        }
    }
    __syncthreads();

    {   // im2col up channels: uim[px][tap*4+ch] fp16, pads zero
        int r = tid >> 6, xx = tid & 63;
        uint32_t arr[28];
        #pragma unroll
        for (int t9 = 0; t9 < 9; ++t9) {
            int dy = t9 / 3, dxp = t9 - dy * 3;
            const float* u4 = winu + ((r + dy) * 66 + xx + dxp) * 4;
            arr[t9 * 2 + 0] = pkhf(__float2half(u4[0]), __float2half(u4[1]));
            arr[t9 * 2 + 1] = pkhf(__float2half(u4[2]), __float2half(u4[3]));
        }
        #pragma unroll
        for (int j = 18; j < 28; ++j) arr[j] = 0u;
        uint4* du = (uint4*)(uim + tid * 112);
        #pragma unroll
        for (int u = 0; u < 7; ++u)
            du[u] = make_uint4(arr[4 * u], arr[4 * u + 1], arr[4 * u + 2], arr[4 * u + 3]);
    }
    __syncthreads();

    const int w = tid >> 5, lane = tid & 31;
    const int rw = w >> 1, colbase = (w & 1) << 5;
    const int t4 = lane >> 3, rowin = lane & 7;
    const int mloc = ((t4 & 1) << 3) + rowin;
    const uint32_t kbyte = (uint32_t)(t4 >> 1) * 16;
    const uint32_t wbx = smem_u32(winx);
    const uint32_t wbu = smem_u32(uim);
    uint32_t baseA[2], baseU[2];
    #pragma unroll
    for (int mb = 0; mb < 2; ++mb) {
        int c = colbase + mb * 16 + mloc;
        baseA[mb] = wbx + (uint32_t)(rw * 66 + c) * 80 + kbyte;
        baseU[mb] = wbu + (uint32_t)(rw * 64 + c) * 112 + kbyte;
    }

    const int cb = (lane & 3) << 1;
    float acc[2][8][4];
    #pragma unroll
    for (int n8 = 0; n8 < 8; ++n8) {
        float b0 = __ldg(bias + n8 * 8 + cb);
        float b1 = __ldg(bias + n8 * 8 + cb + 1);
        #pragma unroll
        for (int mb = 0; mb < 2; ++mb) {
            acc[mb][n8][0] = b0; acc[mb][n8][1] = b1;
            acc[mb][n8][2] = b0; acc[mb][n8][3] = b1;
        }
    }

    for (int t = 0; t < 9; ++t) {
        const int dy = t / 3, dxp = t - dy * 3;
        const uint32_t tapoff = (uint32_t)(dy * 66 + dxp) * 80;
        #pragma unroll
        for (int kc = 0; kc < 2; ++kc) {
            uint32_t ah[2][4];
            #pragma unroll
            for (int mb = 0; mb < 2; ++mb)
                ldmx4(ah[mb], baseA[mb] + tapoff + (uint32_t)kc * 32);
            const uint4* bp = bf1 + ((t * 2 + kc) * 4) * 32 + lane;
            #pragma unroll
            for (int p = 0; p < 4; ++p) {
                uint4 bq = __ldg(bp + p * 32);
                #pragma unroll
                for (int mb = 0; mb < 2; ++mb) {
                    mma16816f(acc[mb][2 * p],     ah[mb], bq.x, bq.y);
                    mma16816f(acc[mb][2 * p + 1], ah[mb], bq.z, bq.w);
                }
            }
        }
    }
    #pragma unroll
    for (int kc = 0; kc < 3; ++kc) {
        uint32_t ah[2][4];
        #pragma unroll
        for (int mb = 0; mb < 2; ++mb)
            ldmx4(ah[mb], baseU[mb] + (uint32_t)kc * 32);
        const uint4* bp = bfu + (kc * 4) * 32 + lane;
        #pragma unroll
        for (int p = 0; p < 4; ++p) {
            uint4 bq = __ldg(bp + p * 32);
            #pragma unroll
            for (int mb = 0; mb < 2; ++mb) {
                mma16816f(acc[mb][2 * p],     ah[mb], bq.x, bq.y);
                mma16816f(acc[mb][2 * p + 1], ah[mb], bq.z, bq.w);
            }
        }
    }

    // ---- epilogue: ReLU -> fp16 hidden, fragment-native word order ----
    // thread quad-index q = lane&3 owns words [q*8, q*8+8) of its pixel
    #pragma unroll
    for (int mb = 0; mb < 2; ++mb) {
        #pragma unroll
        for (int half = 0; half < 2; ++half) {
            int ox = colbase + mb * 16 + (lane >> 2) + half * 8;
            int oy = y0 + rw;
            size_t pix = ((size_t)(n * 64 + oy) * 64 + ox);
            uint32_t oh[8];
            #pragma unroll
            for (int n8 = 0; n8 < 8; ++n8) {
                float v0 = fmaxf(acc[mb][n8][half * 2 + 0], 0.f);
                float v1 = fmaxf(acc[mb][n8][half * 2 + 1], 0.f);
                oh[n8] = pkhf(__float2half(v0), __float2half(v1));
            }
            uint4* dst = reinterpret_cast<uint4*>(g_hidf) + pix * 8 + (lane & 3) * 2;
            dst[0] = make_uint4(oh[0], oh[1], oh[2], oh[3]);
            dst[1] = make_uint4(oh[4], oh[5], oh[6], oh[7]);
        }
    }
}

// ---------------------------------------------------------------------------
// 4) conv2: R10 structure (256 thr, mb=2, n8=4), B via __ldg.
//    Window copies fragment-native hidden verbatim; weight prep compensates.
// ---------------------------------------------------------------------------
__global__ __launch_bounds__(256, 2)
void k_conv2(const uint4* __restrict__ inf,
             const uint4* __restrict__ bf2,
             const float* __restrict__ bias, float* __restrict__ out32) {
    extern __shared__ __align__(16) char smw[];
    constexpr int WS = 72;
    constexpr int WPIX = 6 * 66;
    __half* winf = (__half*)smw;

    const int tid = threadIdx.x;
    const int n  = blockIdx.x >> 4;
    const int y0 = (blockIdx.x & 15) << 2;

    for (int i = tid; i < WPIX; i += 256) {
        int wy = i / 66, wx = i - wy * 66;
        int gy = y0 + wy - 1, gx = wx - 1;
        uint4* df = (uint4*)(winf + i * WS);
        if ((unsigned)gy < 64u && (unsigned)gx < 64u) {
            size_t s = ((size_t)(n * 64 + gy) * 64 + gx) * 8;
            #pragma unroll
            for (int u = 0; u < 8; ++u) df[u] = __ldg(inf + s + u);
        } else {
            uint4 z = make_uint4(0, 0, 0, 0);
            #pragma unroll
            for (int u = 0; u < 8; ++u) df[u] = z;
        }
    }
    __syncthreads();

    const int w = tid >> 5, lane = tid & 31;
    const int rw = w >> 1, colbase = (w & 1) << 5;
    const int t4 = lane >> 3, rowin = lane & 7;
    const int mloc = ((t4 & 1) << 3) + rowin;
    const uint32_t kbyte = (uint32_t)(t4 >> 1) * 16;
    const uint32_t wbh = smem_u32(winf);
    uint32_t baseA[2];
    #pragma unroll
    for (int mb = 0; mb < 2; ++mb) {
        int xx = colbase + mb * 16 + mloc;
        baseA[mb] = wbh + (uint32_t)(rw * 66 + xx) * (WS * 2) + kbyte;
    }

    const int cb = (lane & 3) << 1;
    float acc[2][4][4];
    #pragma unroll
    for (int n8 = 0; n8 < 4; ++n8) {
        float b0 = __ldg(bias + n8 * 8 + cb);
        float b1 = __ldg(bias + n8 * 8 + cb + 1);
        #pragma unroll
        for (int mb = 0; mb < 2; ++mb) {
            acc[mb][n8][0] = b0; acc[mb][n8][1] = b1;
            acc[mb][n8][2] = b0; acc[mb][n8][3] = b1;
        }
    }

    for (int t = 0; t < 9; ++t) {
        const int dy = t / 3, dxp = t - dy * 3;
        const uint32_t tapoff = (uint32_t)(dy * 66 + dxp) * (WS * 2);
        #pragma unroll
        for (int kc = 0; kc < 4; ++kc) {
            uint32_t ah[2][4];
            #pragma unroll
            for (int mb = 0; mb < 2; ++mb)
                ldmx4(ah[mb], baseA[mb] + tapoff + (uint32_t)kc * 32);
            const uint4* bp = bf2 + ((t * 4 + kc) * 2) * 32 + lane;
            #pragma unroll
            for (int p = 0; p < 2; ++p) {
                uint4 bq = __ldg(bp + p * 32);
                #pragma unroll
                for (int mb = 0; mb < 2; ++mb) {
                    mma16816f(acc[mb][2 * p],     ah[mb], bq.x, bq.y);
                    mma16816f(acc[mb][2 * p + 1], ah[mb], bq.z, bq.w);
                }
            }
        }
    }

    #pragma unroll
    for (int mb = 0; mb < 2; ++mb) {
        #pragma unroll
        for (int half = 0; half < 2; ++half) {
            int ox = colbase + mb * 16 + (lane >> 2) + half * 8;
            int oy = y0 + rw;
            float* ob = out32 + (size_t)n * 32 * 4096 + (size_t)oy * 64 + ox;
            #pragma unroll
            for (int n8 = 0; n8 < 4; ++n8) {
                int ch = n8 * 8 + cb;
                ob[(size_t)ch * 4096]       = acc[mb][n8][half * 2 + 0];
                ob[(size_t)(ch + 1) * 4096] = acc[mb][n8][half * 2 + 1];
            }
        }
    }
}

// ---------------------------------------------------------------------------
extern "C" void kernel_launch(void* const* d_in, const int* in_sizes, int n_in,
                              void* d_out, int out_size) {
    const float* x      = (const float*)d_in[0];
    const int*   eidx   = (const int*)  d_in[1];
    const float* w_down = (const float*)d_in[3];
    const float* b_down = (const float*)d_in[4];
    const float* w_e1   = (const float*)d_in[5];
    const float* b_e1   = (const float*)d_in[6];
    const float* w_e2   = (const float*)d_in[7];
    const float* b_e2   = (const float*)d_in[8];
    const float* w_up   = (const float*)d_in[9];
    const float* b_up   = (const float*)d_in[10];
    const float* w_n1   = (const float*)d_in[11];
    const float* b_n1   = (const float*)d_in[12];
    const float* w_n2   = (const float*)d_in[13];
    const float* b_n2   = (const float*)d_in[14];
    float* out = (float*)d_out;

    void *p_hidf, *p_B1, *p_Bu, *p_B2;
    cudaGetSymbolAddress(&p_hidf, g_hidf);
    cudaGetSymbolAddress(&p_B1, g_Bf1);
    cudaGetSymbolAddress(&p_Bu, g_Bfu);
    cudaGetSymbolAddress(&p_B2, g_Bf2);

    const int sm1 = 31680 + 6336 + 28672;   // 66688 B
    const int sm2 = 6 * 66 * 72 * 2;        // 57024 B
    cudaFuncSetAttribute((const void*)k_conv1,
                         cudaFuncAttributeMaxDynamicSharedMemorySize, sm1);
    cudaFuncSetAttribute((const void*)k_conv2,
                         cudaFuncAttributeMaxDynamicSharedMemorySize, sm2);

    // 1) downsample (+zero g_agg) fused with weight prep
    k_down_wprep<<<1044, 256>>>(x, w_down, b_down, w_n1, w_n2);
    // 2) fused edge network + scatter-add (FFMA2)
    k_edge<<<NEDGE, 256>>>(eidx, w_e1, b_e1, w_e2, b_e2);
    // 3) conv1: R10 tiling, wide fragment-native epilogue
    k_conv1<<<4096, 256, sm1>>>(x, w_up, b_up,
        (const uint4*)p_B1, (const uint4*)p_Bu, b_n1);
    // 4) conv2: R10 tiling, permuted weight fragments
    k_conv2<<<4096, 256, sm2>>>((const uint4*)p_hidf,
        (const uint4*)p_B2, b_n2, out);
}

// round 14
// speedup vs baseline: 1.0238x; 1.0018x over previous
#include <cuda_runtime.h>
#include <cuda_bf16.h>
#include <cuda_fp16.h>
#include <cstdint>
#include <cstddef>

#define NNODE 256
#define NEDGE 4096

typedef unsigned long long ull;

// ---------------- device scratch (no runtime allocation allowed) ------------
__device__ float g_xd [NNODE * 4 * 32 * 32];                    //  4 MB
__device__ float g_agg[NNODE * 4 * 32 * 32];                    //  4 MB
// hidden: fp16, 64 ch per pixel, FRAGMENT-NATIVE word order:
//   word W (uint32) = q*8 + n8 holds channel pair c = 2*(n8*4+q), c+1
//   uint4 u = W>>2 maps to A-fragment plane (kc = u>>1, khalf = u&1)
__device__ __align__(16) __half g_hidf[(size_t)NNODE * 4096 * 64];   // 134 MB
// single-fp16 weights, HMMA B-fragment order, n8-PAIR-fastest (uint4/lane)
__device__ __align__(16) uint4 g_Bf1[18 * 4 * 32];   // conv1 x-part  [chunk<18][p<4][lane]
__device__ __align__(16) uint4 g_Bfu[ 3 * 4 * 32];   // conv1 up-part [chunk<3][p<4][lane]
__device__ __align__(16) uint4 g_Bf2[36 * 2 * 32];   // conv2         [chunk<36][p<2][lane]

// ---------------- helpers ---------------------------------------------------
__device__ __forceinline__ uint32_t smem_u32(const void* p) {
    uint32_t a;
    asm("{ .reg .u64 t; cvta.to.shared.u64 t, %1; cvt.u32.u64 %0, t; }"
        : "=r"(a) : "l"(p));
    return a;
}
__device__ __forceinline__ void ldmx4(uint32_t* r, uint32_t addr) {
    asm volatile("ldmatrix.sync.aligned.m8n8.x4.shared.b16 {%0,%1,%2,%3}, [%4];"
                 : "=r"(r[0]), "=r"(r[1]), "=r"(r[2]), "=r"(r[3]) : "r"(addr));
}
__device__ __forceinline__ void mma16816f(float* d, const uint32_t* a,
                                          uint32_t b0, uint32_t b1) {
    asm volatile("mma.sync.aligned.m16n8k16.row.col.f32.f16.f16.f32 "
                 "{%0,%1,%2,%3},{%4,%5,%6,%7},{%8,%9},{%0,%1,%2,%3};"
                 : "+f"(d[0]), "+f"(d[1]), "+f"(d[2]), "+f"(d[3])
                 : "r"(a[0]), "r"(a[1]), "r"(a[2]), "r"(a[3]), "r"(b0), "r"(b1));
}
__device__ __forceinline__ uint32_t pkhf(__half a, __half b) {
    __half2 t = __halves2half2(a, b);
    return *reinterpret_cast<uint32_t*>(&t);
}
__device__ __forceinline__ ull pk2(float a, float b) {
    ull r; asm("mov.b64 %0, {%1, %2};" : "=l"(r) : "f"(a), "f"(b)); return r;
}
__device__ __forceinline__ void fma2(ull& d, ull a, ull b) {
    asm("fma.rn.f32x2 %0, %1, %2, %0;" : "+l"(d) : "l"(a), "l"(b));
}
__device__ __forceinline__ void upk2(ull v, float& a, float& b) {
    asm("mov.b64 {%0, %1}, %2;" : "=f"(a), "=f"(b) : "l"(v));
}
__device__ __forceinline__ void sts128(uint32_t addr, uint4 v) {
    asm volatile("st.shared.v4.b32 [%0], {%1,%2,%3,%4};"
                 :: "r"(addr), "r"(v.x), "r"(v.y), "r"(v.z), "r"(v.w) : "memory");
}

// ---------------------------------------------------------------------------
// 1) merged: downsample + zero g_agg (blocks 0..1023)  |  weight prep (1024+)
// ---------------------------------------------------------------------------
__global__ __launch_bounds__(256) void k_down_wprep(const float* __restrict__ x,
                                                    const float* __restrict__ w,
                                                    const float* __restrict__ b,
                                                    const float* __restrict__ w1,
                                                    const float* __restrict__ w2) {
    if (blockIdx.x < 1024) {
        int idx = blockIdx.x * 256 + threadIdx.x;
        int n = idx >> 10, p = (idx >> 5) & 31, q = idx & 31;
        float a0 = __ldg(b + 0), a1 = __ldg(b + 1), a2 = __ldg(b + 2), a3 = __ldg(b + 3);
        const float* xp = x + (size_t)n * 32 * 4096 + (2 * p) * 64 + 2 * q;
        const float4* wq = (const float4*)w;
        #pragma unroll 4
        for (int c = 0; c < 32; ++c) {
            float2 va = __ldg((const float2*)(xp + c * 4096));
            float2 vb = __ldg((const float2*)(xp + c * 4096 + 64));
            float4 w0 = __ldg(wq + c);
            float4 w1v = __ldg(wq + 32 + c);
            float4 w2v = __ldg(wq + 64 + c);
            float4 w3v = __ldg(wq + 96 + c);
            a0 += va.x * w0.x + va.y * w0.y + vb.x * w0.z + vb.y * w0.w;
            a1 += va.x * w1v.x + va.y * w1v.y + vb.x * w1v.z + vb.y * w1v.w;
            a2 += va.x * w2v.x + va.y * w2v.y + vb.x * w2v.z + vb.y * w2v.w;
            a3 += va.x * w3v.x + va.y * w3v.y + vb.x * w3v.z + vb.y * w3v.w;
        }
        float* op = g_xd + n * 4096 + p * 32 + q;
        op[0] = a0; op[1024] = a1; op[2048] = a2; op[3072] = a3;
        float* ap = g_agg + n * 4096 + p * 32 + q;
        ap[0] = 0.f; ap[1024] = 0.f; ap[2048] = 0.f; ap[3072] = 0.f;
        return;
    }
    int i = (blockIdx.x - 1024) * 256 + threadIdx.x;
    if (i < 2304) {                          // conv1 x-part: 18 chunks * 4p * 32
        int chunk = i >> 7, rem = i & 127;
        int p = rem >> 5, lane = rem & 31;
        int t = chunk >> 1, kc = chunk & 1;
        int cb = kc * 16 + ((lane & 3) << 1);
        uint32_t v[4];
        #pragma unroll
        for (int e2 = 0; e2 < 2; ++e2) {
            int o = (2 * p + e2) * 8 + (lane >> 2);
            v[e2 * 2 + 0] = pkhf(__float2half(__ldg(w1 + (size_t)(o * 36 + cb)     * 9 + t)),
                                 __float2half(__ldg(w1 + (size_t)(o * 36 + cb + 1) * 9 + t)));
            v[e2 * 2 + 1] = pkhf(__float2half(__ldg(w1 + (size_t)(o * 36 + cb + 8) * 9 + t)),
                                 __float2half(__ldg(w1 + (size_t)(o * 36 + cb + 9) * 9 + t)));
        }
        g_Bf1[i] = make_uint4(v[0], v[1], v[2], v[3]);
    } else if (i < 2304 + 384) {             // conv1 up-part: 3 chunks * 4p * 32
        int j = i - 2304;
        int chunk = j >> 7, rem = j & 127;
        int p = rem >> 5, lane = rem & 31;
        int k0 = chunk * 16 + ((lane & 3) << 1);
        uint32_t v[4];
        #pragma unroll
        for (int e2 = 0; e2 < 2; ++e2) {
            int o = (2 * p + e2) * 8 + (lane >> 2);
            float f[4];
            #pragma unroll
            for (int q = 0; q < 4; ++q) {
                int k = k0 + (q >> 1) * 8 + (q & 1);
                f[q] = (k < 36)
                     ? __ldg(w1 + (size_t)(o * 36 + 32 + (k & 3)) * 9 + (k >> 2))
                     : 0.f;
            }
            v[e2 * 2 + 0] = pkhf(__float2half(f[0]), __float2half(f[1]));
            v[e2 * 2 + 1] = pkhf(__float2half(f[2]), __float2half(f[3]));
        }
        g_Bfu[j] = make_uint4(v[0], v[1], v[2], v[3]);
    } else if (i < 2688 + 2304) {            // conv2: 36 chunks * 2p * 32
        // fragment-native hidden: channel(kc,k) = (k>>1)*8 + kc*2 + (k&1)
        int j = i - 2688;
        int chunk = j >> 6, rem = j & 63;
        int p = rem >> 5, lane = rem & 31;
        int t = chunk >> 2, kc = chunk & 3;
        int c0 = ((lane & 3) << 3) + kc * 2;
        uint32_t v[4];
        #pragma unroll
        for (int e2 = 0; e2 < 2; ++e2) {
            int o = (2 * p + e2) * 8 + (lane >> 2);
            v[e2 * 2 + 0] = pkhf(__float2half(__ldg(w2 + (size_t)(o * 64 + c0)      * 9 + t)),
                                 __float2half(__ldg(w2 + (size_t)(o * 64 + c0 + 1)  * 9 + t)));
            v[e2 * 2 + 1] = pkhf(__float2half(__ldg(w2 + (size_t)(o * 64 + c0 + 32) * 9 + t)),
                                 __float2half(__ldg(w2 + (size_t)(o * 64 + c0 + 33) * 9 + t)));
        }
        g_Bf2[j] = make_uint4(v[0], v[1], v[2], v[3]);
    }
}

// ---------------------------------------------------------------------------
// 2) fused edge network + scatter, FFMA2 (validated R10)
// ---------------------------------------------------------------------------
__global__ __launch_bounds__(256) void k_edge(const int* __restrict__ eidx,
                                              const float* __restrict__ we1,
                                              const float* __restrict__ be1,
                                              const float* __restrict__ we2,
                                              const float* __restrict__ be2) {
    __shared__ float sIn[8][34][34];
    const int e = blockIdx.x;
    const int row = eidx[e];
    const int col = eidx[NEDGE + e];
    const int tid = threadIdx.x;

    for (int i = tid; i < 1056; i += 256) {
        int ch = i / 132, r = i - ch * 132;
        int py, px;
        if (r < 34)      { py = 0;  px = r; }
        else if (r < 68) { py = 33; px = r - 34; }
        else { int rr = r - 68; py = 1 + (rr >> 1); px = (rr & 1) ? 33 : 0; }
        sIn[ch][py][px] = 0.f;
    }
    for (int i = tid; i < 2048; i += 256) {
        int ch = i >> 8, p4 = i & 255;
        int node = (ch < 4) ? row : col;
        float4 v = __ldg((const float4*)(g_xd + node * 4096 + (ch & 3) * 1024) + p4);
        int py = p4 >> 3, px = (p4 & 7) << 2;
        float* d = &sIn[ch][py + 1][px + 1];
        d[0] = v.x; d[1] = v.y; d[2] = v.z; d[3] = v.w;
    }
    __syncthreads();

    const int og   = tid >> 7;
    const int unit = tid & 127;
    const int ry   = unit >> 2;
    const int cx0  = (unit & 3) << 3;
    const int o0 = og * 2, o1 = og * 2 + 1;

    ull acc1[8];
    { ull bp = pk2(__ldg(be1 + o0), __ldg(be1 + o1));
      #pragma unroll
      for (int j = 0; j < 8; ++j) acc1[j] = bp; }
    #pragma unroll
    for (int ci = 0; ci < 8; ++ci) {
        ull v[3][10];
        #pragma unroll
        for (int d = 0; d < 3; ++d)
            #pragma unroll
            for (int c = 0; c < 10; ++c) {
                float f = sIn[ci][ry + d][cx0 + c];
                v[d][c] = pk2(f, f);
            }
        #pragma unroll
        for (int t = 0; t < 9; ++t) {
            int dy = t / 3, dx = t - dy * 3;
            ull wp = pk2(__ldg(we1 + o0 * 72 + ci * 9 + t),
                         __ldg(we1 + o1 * 72 + ci * 9 + t));
            #pragma unroll
            for (int j = 0; j < 8; ++j) fma2(acc1[j], v[dy][dx + j], wp);
        }
    }
    __syncthreads();
    #pragma unroll
    for (int j = 0; j < 8; ++j) {
        float a, b; upk2(acc1[j], a, b);
        sIn[o0][ry + 1][cx0 + 1 + j] = fmaxf(a, 0.f);
        sIn[o1][ry + 1][cx0 + 1 + j] = fmaxf(b, 0.f);
    }
    __syncthreads();

    ull acc2[8];
    { ull bp = pk2(__ldg(be2 + o0), __ldg(be2 + o1));
      #pragma unroll
      for (int j = 0; j < 8; ++j) acc2[j] = bp; }
    #pragma unroll
    for (int ci = 0; ci < 4; ++ci) {
        ull v[3][10];
        #pragma unroll
        for (int d = 0; d < 3; ++d)
            #pragma unroll
            for (int c = 0; c < 10; ++c) {
                float f = sIn[ci][ry + d][cx0 + c];
                v[d][c] = pk2(f, f);
            }
        #pragma unroll
        for (int t = 0; t < 9; ++t) {
            int dy = t / 3, dx = t - dy * 3;
            ull wp = pk2(__ldg(we2 + o0 * 36 + ci * 9 + t),
                         __ldg(we2 + o1 * 36 + ci * 9 + t));
            #pragma unroll
            for (int j = 0; j < 8; ++j) fma2(acc2[j], v[dy][dx + j], wp);
        }
    }
    float* ag0 = g_agg + row * 4096 + o0 * 1024 + ry * 32 + cx0;
    float* ag1 = g_agg + row * 4096 + o1 * 1024 + ry * 32 + cx0;
    #pragma unroll
    for (int j = 0; j < 8; ++j) {
        float a, b; upk2(acc2[j], a, b);
        atomicAdd(ag0 + j, fmaxf(a, 0.f));
        atomicAdd(ag1 + j, fmaxf(b, 0.f));
    }
}

// ---------------------------------------------------------------------------
// 3) conv1: A-operand-native window planes.
//    winx: [6 rows][4 planes (kc*2+h)][66 cols][16B]  = 25344 B
//    winu: fp32 up [396][4]                            =  6336 B
//    uim : [6 planes (kc*2+h)][256 px][16B]            = 24576 B
//    ldmatrix tile rows = consecutive cols -> 128B contiguous (4 wf / x4).
// ---------------------------------------------------------------------------
__global__ __launch_bounds__(256, 2)
void k_conv1(const float* __restrict__ x,
             const float* __restrict__ wup, const float* __restrict__ bup,
             const uint4* __restrict__ bf1, const uint4* __restrict__ bfu,
             const float* __restrict__ bias) {
    extern __shared__ __align__(16) char smw[];
    char*  winx = smw;                       // 25344 B
    float* winu = (float*)(smw + 25344);     //  6336 B
    char*  uim  = smw + 31680;               // 24576 B
    constexpr uint32_t XROW = 4 * 66 * 16;   // 4224: winx row stride
    constexpr uint32_t XPL  = 66 * 16;       // 1056: winx plane stride
    constexpr uint32_t UPL  = 256 * 16;      // 4096: uim plane stride

    const int tid = threadIdx.x;
    const int n  = blockIdx.x >> 4;
    const int y0 = (blockIdx.x & 15) << 2;
    const uint32_t wbx = smem_u32(winx);
    const uint32_t wbu = smem_u32(uim);

    // ---- stage halo: x channels -> 4 winx planes; up(agg) fp32 -> winu ----
    for (int i = tid; i < 396; i += 256) {
        int wy = i / 66, wx = i - wy * 66;
        int gy = y0 + wy - 1, gx = wx - 1;
        uint32_t pb = wbx + (uint32_t)wy * XROW + (uint32_t)wx * 16;
        float4* du = (float4*)(winu + i * 4);
        if ((unsigned)gy < 64u && (unsigned)gx < 64u) {
            const float* ag = g_agg + n * 4096 + (gy >> 1) * 32 + (gx >> 1);
            const int ab = ((gy & 1) << 1) + (gx & 1);
            float up[4];
            #pragma unroll
            for (int o = 0; o < 4; ++o) {
                float v = __ldg(bup + o);
                #pragma unroll
                for (int c = 0; c < 4; ++c)
                    v += ag[c * 1024] * __ldg(wup + ((c * 4 + o) << 2) + ab);
                up[o] = v;
            }
            *du = make_float4(up[0], up[1], up[2], up[3]);
            uint32_t ph[16];
            const float* xp = x + (size_t)n * 32 * 4096 + gy * 64 + gx;
            #pragma unroll
            for (int c2 = 0; c2 < 16; ++c2)
                ph[c2] = pkhf(__float2half(__ldg(xp + (2 * c2) * 4096)),
                              __float2half(__ldg(xp + (2 * c2 + 1) * 4096)));
            #pragma unroll
            for (int u = 0; u < 4; ++u)
                sts128(pb + u * XPL,
                       make_uint4(ph[4 * u], ph[4 * u + 1], ph[4 * u + 2], ph[4 * u + 3]));
        } else {
            uint4 z = make_uint4(0, 0, 0, 0);
            #pragma unroll
            for (int u = 0; u < 4; ++u) sts128(pb + u * XPL, z);
            *du = make_float4(0.f, 0.f, 0.f, 0.f);
        }
    }
    __syncthreads();

    {   // im2col up channels into 6 uim planes (words 4u..4u+3 -> plane u)
        int r = tid >> 6, xx = tid & 63;
        uint32_t arr[24];
        #pragma unroll
        for (int t9 = 0; t9 < 9; ++t9) {
            int dy = t9 / 3, dxp = t9 - dy * 3;
            const float* u4 = winu + ((r + dy) * 66 + xx + dxp) * 4;
            arr[t9 * 2 + 0] = pkhf(__float2half(u4[0]), __float2half(u4[1]));
            arr[t9 * 2 + 1] = pkhf(__float2half(u4[2]), __float2half(u4[3]));
        }
        #pragma unroll
        for (int j = 18; j < 24; ++j) arr[j] = 0u;
        uint32_t ub = wbu + (uint32_t)tid * 16;
        #pragma unroll
        for (int u = 0; u < 6; ++u)
            sts128(ub + u * UPL,
                   make_uint4(arr[4 * u], arr[4 * u + 1], arr[4 * u + 2], arr[4 * u + 3]));
    }
    __syncthreads();

    const int w = tid >> 5, lane = tid & 31;
    const int rw = w >> 1, colbase = (w & 1) << 5;
    const int t4 = lane >> 3, rowin = lane & 7;
    const int mloc = ((t4 & 1) << 3) + rowin;
    const uint32_t hpl = (uint32_t)(t4 >> 1);     // khalf plane select
    // base addresses: per-lane, plane-relative
    const uint32_t baseX = wbx + (uint32_t)rw * XROW + hpl * XPL
                         + (uint32_t)(colbase + mloc) * 16;
    const uint32_t baseU = wbu + hpl * UPL
                         + (uint32_t)(rw * 64 + colbase + mloc) * 16;

    const int cb = (lane & 3) << 1;
    float acc[2][8][4];
    #pragma unroll
    for (int n8 = 0; n8 < 8; ++n8) {
        float b0 = __ldg(bias + n8 * 8 + cb);
        float b1 = __ldg(bias + n8 * 8 + cb + 1);
        #pragma unroll
        for (int mb = 0; mb < 2; ++mb) {
            acc[mb][n8][0] = b0; acc[mb][n8][1] = b1;
            acc[mb][n8][2] = b0; acc[mb][n8][3] = b1;
        }
    }

    for (int t = 0; t < 9; ++t) {
        const int dy = t / 3, dxp = t - dy * 3;
        const uint32_t tb = baseX + (uint32_t)dy * XROW + (uint32_t)dxp * 16;
        #pragma unroll
        for (int kc = 0; kc < 2; ++kc) {
            uint32_t ah[2][4];
            #pragma unroll
            for (int mb = 0; mb < 2; ++mb)
                ldmx4(ah[mb], tb + (uint32_t)kc * (2 * XPL) + (uint32_t)(mb * 16) * 16);
            const uint4* bp = bf1 + ((t * 2 + kc) * 4) * 32 + lane;
            #pragma unroll
            for (int p = 0; p < 4; ++p) {
                uint4 bq = __ldg(bp + p * 32);
                #pragma unroll
                for (int mb = 0; mb < 2; ++mb) {
                    mma16816f(acc[mb][2 * p],     ah[mb], bq.x, bq.y);
                    mma16816f(acc[mb][2 * p + 1], ah[mb], bq.z, bq.w);
                }
            }
        }
    }
    #pragma unroll
    for (int kc = 0; kc < 3; ++kc) {
        uint32_t ah[2][4];
        #pragma unroll
        for (int mb = 0; mb < 2; ++mb)
            ldmx4(ah[mb], baseU + (uint32_t)kc * (2 * UPL) + (uint32_t)(mb * 16) * 16);
        const uint4* bp = bfu + (kc * 4) * 32 + lane;
        #pragma unroll
        for (int p = 0; p < 4; ++p) {
            uint4 bq = __ldg(bp + p * 32);
            #pragma unroll
            for (int mb = 0; mb < 2; ++mb) {
                mma16816f(acc[mb][2 * p],     ah[mb], bq.x, bq.y);
                mma16816f(acc[mb][2 * p + 1], ah[mb], bq.z, bq.w);
            }
        }
    }

    // ---- epilogue: ReLU -> fp16 hidden, fragment-native word order ----
    #pragma unroll
    for (int mb = 0; mb < 2; ++mb) {
        #pragma unroll
        for (int half = 0; half < 2; ++half) {
            int ox = colbase + mb * 16 + (lane >> 2) + half * 8;
            int oy = y0 + rw;
            size_t pix = ((size_t)(n * 64 + oy) * 64 + ox);
            uint32_t oh[8];
            #pragma unroll
            for (int n8 = 0; n8 < 8; ++n8) {
                float v0 = fmaxf(acc[mb][n8][half * 2 + 0], 0.f);
                float v1 = fmaxf(acc[mb][n8][half * 2 + 1], 0.f);
                oh[n8] = pkhf(__float2half(v0), __float2half(v1));
            }
            uint4* dst = reinterpret_cast<uint4*>(g_hidf) + pix * 8 + (lane & 3) * 2;
            dst[0] = make_uint4(oh[0], oh[1], oh[2], oh[3]);
            dst[1] = make_uint4(oh[4], oh[5], oh[6], oh[7]);
        }
    }
}

// ---------------------------------------------------------------------------
// 4) conv2: A-operand-native window: [6 rows][8 planes][66 cols][16B] = 50688 B
//    hidden uint4 u -> plane u directly (fragment-native storage).
// ---------------------------------------------------------------------------
__global__ __launch_bounds__(256, 2)
void k_conv2(const uint4* __restrict__ inf,
             const uint4* __restrict__ bf2,
             const float* __restrict__ bias, float* __restrict__ out32) {
    extern __shared__ __align__(16) char smw[];
    constexpr uint32_t XPL  = 66 * 16;        // 1056
    constexpr uint32_t XROW = 8 * XPL;        // 8448

    const int tid = threadIdx.x;
    const int n  = blockIdx.x >> 4;
    const int y0 = (blockIdx.x & 15) << 2;
    const uint32_t wb = smem_u32(smw);

    for (int i = tid; i < 396; i += 256) {
        int wy = i / 66, wx = i - wy * 66;
        int gy = y0 + wy - 1, gx = wx - 1;
        uint32_t pb = wb + (uint32_t)wy * XROW + (uint32_t)wx * 16;
        if ((unsigned)gy < 64u && (unsigned)gx < 64u) {
            size_t s = ((size_t)(n * 64 + gy) * 64 + gx) * 8;
            #pragma unroll
            for (int u = 0; u < 8; ++u)
                sts128(pb + u * XPL, __ldg(inf + s + u));
        } else {
            uint4 z = make_uint4(0, 0, 0, 0);
            #pragma unroll
            for (int u = 0; u < 8; ++u) sts128(pb + u * XPL, z);
        }
    }
    __syncthreads();

    const int w = tid >> 5, lane = tid & 31;
    const int rw = w >> 1, colbase = (w & 1) << 5;
    const int t4 = lane >> 3, rowin = lane & 7;
    const int mloc = ((t4 & 1) << 3) + rowin;
    const uint32_t hpl = (uint32_t)(t4 >> 1);
    const uint32_t baseA = wb + (uint32_t)rw * XROW + hpl * XPL
                         + (uint32_t)(colbase + mloc) * 16;

    const int cb = (lane & 3) << 1;
    float acc[2][4][4];
    #pragma unroll
    for (int n8 = 0; n8 < 4; ++n8) {
        float b0 = __ldg(bias + n8 * 8 + cb);
        float b1 = __ldg(bias + n8 * 8 + cb + 1);
        #pragma unroll
        for (int mb = 0; mb < 2; ++mb) {
            acc[mb][n8][0] = b0; acc[mb][n8][1] = b1;
            acc[mb][n8][2] = b0; acc[mb][n8][3] = b1;
        }
    }

    for (int t = 0; t < 9; ++t) {
        const int dy = t / 3, dxp = t - dy * 3;
        const uint32_t tb = baseA + (uint32_t)dy * XROW + (uint32_t)dxp * 16;
        #pragma unroll
        for (int kc = 0; kc < 4; ++kc) {
            uint32_t ah[2][4];
            #pragma unroll
            for (int mb = 0; mb < 2; ++mb)
                ldmx4(ah[mb], tb + (uint32_t)kc * (2 * XPL) + (uint32_t)(mb * 16) * 16);
            const uint4* bp = bf2 + ((t * 4 + kc) * 2) * 32 + lane;
            #pragma unroll
            for (int p = 0; p < 2; ++p) {
                uint4 bq = __ldg(bp + p * 32);
                #pragma unroll
                for (int mb = 0; mb < 2; ++mb) {
                    mma16816f(acc[mb][2 * p],     ah[mb], bq.x, bq.y);
                    mma16816f(acc[mb][2 * p + 1], ah[mb], bq.z, bq.w);
                }
            }
        }
    }

    #pragma unroll
    for (int mb = 0; mb < 2; ++mb) {
        #pragma unroll
        for (int half = 0; half < 2; ++half) {
            int ox = colbase + mb * 16 + (lane >> 2) + half * 8;
            int oy = y0 + rw;
            float* ob = out32 + (size_t)n * 32 * 4096 + (size_t)oy * 64 + ox;
            #pragma unroll
            for (int n8 = 0; n8 < 4; ++n8) {
                int ch = n8 * 8 + cb;
                ob[(size_t)ch * 4096]       = acc[mb][n8][half * 2 + 0];
                ob[(size_t)(ch + 1) * 4096] = acc[mb][n8][half * 2 + 1];
            }
        }
    }
}

// ---------------------------------------------------------------------------
extern "C" void kernel_launch(void* const* d_in, const int* in_sizes, int n_in,
                              void* d_out, int out_size) {
    const float* x      = (const float*)d_in[0];
    const int*   eidx   = (const int*)  d_in[1];
    const float* w_down = (const float*)d_in[3];
    const float* b_down = (const float*)d_in[4];
    const float* w_e1   = (const float*)d_in[5];
    const float* b_e1   = (const float*)d_in[6];
    const float* w_e2   = (const float*)d_in[7];
    const float* b_e2   = (const float*)d_in[8];
    const float* w_up   = (const float*)d_in[9];
    const float* b_up   = (const float*)d_in[10];
    const float* w_n1   = (const float*)d_in[11];
    const float* b_n1   = (const float*)d_in[12];
    const float* w_n2   = (const float*)d_in[13];
    const float* b_n2   = (const float*)d_in[14];
    float* out = (float*)d_out;

    void *p_hidf, *p_B1, *p_Bu, *p_B2;
    cudaGetSymbolAddress(&p_hidf, g_hidf);
    cudaGetSymbolAddress(&p_B1, g_Bf1);
    cudaGetSymbolAddress(&p_Bu, g_Bfu);
    cudaGetSymbolAddress(&p_B2, g_Bf2);

    const int sm1 = 25344 + 6336 + 24576;   // 56256 B
    const int sm2 = 6 * 8448;               // 50688 B
    cudaFuncSetAttribute((const void*)k_conv1,
                         cudaFuncAttributeMaxDynamicSharedMemorySize, sm1);
    cudaFuncSetAttribute((const void*)k_conv2,
                         cudaFuncAttributeMaxDynamicSharedMemorySize, sm2);

    // 1) downsample (+zero g_agg) fused with weight prep
    k_down_wprep<<<1044, 256>>>(x, w_down, b_down, w_n1, w_n2);
    // 2) fused edge network + scatter-add (FFMA2)
    k_edge<<<NEDGE, 256>>>(eidx, w_e1, b_e1, w_e2, b_e2);
    // 3) conv1: plane-native window, coalesced ldmatrix
    k_conv1<<<4096, 256, sm1>>>(x, w_up, b_up,
        (const uint4*)p_B1, (const uint4*)p_Bu, b_n1);
    // 4) conv2: plane-native window, coalesced ldmatrix
    k_conv2<<<4096, 256, sm2>>>((const uint4*)p_hidf,
        (const uint4*)p_B2, b_n2, out);
}